// round 3
// baseline (speedup 1.0000x reference)
#include <cuda_runtime.h>

// Problem constants (from reference): B=128, S=256, D=1024, BETA=1.0
#define BB 128
#define SS 256
#define DD 1024
#define BETA_F 1.0f

#define SPLIT 4            // blocks per batch
#define WARPS 8            // warps per block
#define NBLOCKS (BB * SPLIT)
#define NTHREADS (WARPS * 32)

__device__ float g_partials[NBLOCKS];
__device__ unsigned g_ctr = 0;   // self-resetting via atomicInc wraparound

__global__ __launch_bounds__(NTHREADS, 4)
void bridge_loss_fused(const float* __restrict__ bridges,
                       const int*   __restrict__ b_inx,
                       const int*   __restrict__ neg_i,
                       const int*   __restrict__ neg_j,
                       float*       __restrict__ out)
{
    const int b    = blockIdx.x / SPLIT;
    const int part = blockIdx.x % SPLIT;
    const int warp = threadIdx.x >> 5;
    const int lane = threadIdx.x & 31;
    const int wib  = part * WARPS + warp;          // warp index within batch: 0..31

    // head / tail rows for this batch in shared memory (8 KB)
    __shared__ float4 sh_h[DD / 4];
    __shared__ float4 sh_t[DD / 4];

    const float4* base = (const float4*)(bridges + (size_t)b * SS * DD);
    const float4* hp   = base;                               // s = 0
    const float4* tp4  = base + (size_t)(SS - 1) * (DD / 4); // s = S-1

    // 256 threads, 256 float4 per row: one each
    sh_h[threadIdx.x] = hp [threadIdx.x];
    sh_t[threadIdx.x] = tp4[threadIdx.x];
    __syncthreads();

    const float th = (float)b_inx[b * SS];
    const float tt = (float)b_inx[b * SS + SS - 1];
    const float inv_den = 1.0f / (tt - th);

    float wloss = 0.0f;

    for (int r = wib; r < SS - 2; r += SPLIT * WARPS) {
        const int s = r + 1;
        const float tpv   = (float)b_inx[b * SS + s];
        const float alpha = (tpv - th) * inv_den;
        const float sigma = alpha * (tt - tpv);
        const float inv   = 1.0f / (2.0f * sigma * sigma);

        const int ni = neg_i[b * (SS - 2) + r];
        const int nj = neg_j[b * (SS - 2) + r];

        const float4* pp = (const float4*)(bridges + ((size_t)b  * SS + s ) * DD);
        const float4* np = (const float4*)(bridges + ((size_t)ni * SS + nj) * DD);

        float acc = 0.0f;   // sum over d of (xn^2 - xp^2)
#pragma unroll
        for (int half = 0; half < 2; half++) {
            float4 p[4], n[4];
#pragma unroll
            for (int j = 0; j < 4; j++) {
                const int idx = lane + (half * 4 + j) * 32;
                p[j] = pp[idx];
                n[j] = np[idx];
            }
#pragma unroll
            for (int j = 0; j < 4; j++) {
                const int idx = lane + (half * 4 + j) * 32;
                const float4 hv = sh_h[idx], tv = sh_t[idx];
                const float4 pv = p[j],      nv = n[j];
                const float mx = fmaf(alpha, tv.x - hv.x, hv.x);
                const float my = fmaf(alpha, tv.y - hv.y, hv.y);
                const float mz = fmaf(alpha, tv.z - hv.z, hv.z);
                const float mw = fmaf(alpha, tv.w - hv.w, hv.w);
                const float xpx = pv.x - mx, xpy = pv.y - my, xpz = pv.z - mz, xpw = pv.w - mw;
                const float xnx = nv.x - mx, xny = nv.y - my, xnz = nv.z - mz, xnw = nv.w - mw;
                acc = fmaf(xnx, xnx, acc); acc = fmaf(-xpx, xpx, acc);
                acc = fmaf(xny, xny, acc); acc = fmaf(-xpy, xpy, acc);
                acc = fmaf(xnz, xnz, acc); acc = fmaf(-xpz, xpz, acc);
                acc = fmaf(xnw, xnw, acc); acc = fmaf(-xpw, xpw, acc);
            }
        }

        // warp tree reduce
#pragma unroll
        for (int off = 16; off; off >>= 1)
            acc += __shfl_xor_sync(0xffffffffu, acc, off);

        const float cur = fmaf(acc, inv, BETA_F);
        if (cur > 0.0f) wloss += cur;
    }

    __shared__ float sm[WARPS];
    __shared__ bool  amLast;
    if (lane == 0) sm[warp] = wloss;
    __syncthreads();
    if (threadIdx.x == 0) {
        float t = 0.0f;
#pragma unroll
        for (int w = 0; w < WARPS; w++) t += sm[w];
        g_partials[blockIdx.x] = t;
        __threadfence();
        // wraps to 0 when old == NBLOCKS-1 -> self-resetting for graph replay
        unsigned old = atomicInc(&g_ctr, NBLOCKS - 1);
        amLast = (old == NBLOCKS - 1);
    }
    __syncthreads();

    if (amLast) {
        // Deterministic final reduction: fixed tree order over g_partials.
        __shared__ float fin[NTHREADS];
        float t = 0.0f;
#pragma unroll
        for (int k = 0; k < NBLOCKS / NTHREADS; k++)
            t += g_partials[threadIdx.x + k * NTHREADS];
        fin[threadIdx.x] = t;
        __syncthreads();
#pragma unroll
        for (int st = NTHREADS / 2; st > 0; st >>= 1) {
            if ((int)threadIdx.x < st) fin[threadIdx.x] += fin[threadIdx.x + st];
            __syncthreads();
        }
        if (threadIdx.x == 0) out[0] = fin[0] / (float)BB;
    }
}

extern "C" void kernel_launch(void* const* d_in, const int* in_sizes, int n_in,
                              void* d_out, int out_size)
{
    const float* bridges = (const float*)d_in[0];
    const int*   b_inx   = (const int*)  d_in[1];
    const int*   neg_i   = (const int*)  d_in[2];
    const int*   neg_j   = (const int*)  d_in[3];

    bridge_loss_fused<<<NBLOCKS, NTHREADS>>>(bridges, b_inx, neg_i, neg_j,
                                             (float*)d_out);
}

// round 4
// speedup vs baseline: 1.3951x; 1.3951x over previous
#include <cuda_runtime.h>

// Problem constants (from reference): B=128, S=256, D=1024, BETA=1.0
#define BB 128
#define SS 256
#define DD 1024
#define BETA_F 1.0f

#define SPLIT 4            // blocks per batch
#define WARPS 8            // warps per block
#define NBLOCKS (BB * SPLIT)
#define NTHREADS (WARPS * 32)

__device__ float g_partials[NBLOCKS];
__device__ unsigned g_ctr = 0;   // self-resetting via atomicInc wraparound

__global__ __launch_bounds__(NTHREADS, 2)
void bridge_loss_fused(const float* __restrict__ bridges,
                       const int*   __restrict__ b_inx,
                       const int*   __restrict__ neg_i,
                       const int*   __restrict__ neg_j,
                       float*       __restrict__ out)
{
    const int b    = blockIdx.x / SPLIT;
    const int part = blockIdx.x % SPLIT;
    const int warp = threadIdx.x >> 5;
    const int lane = threadIdx.x & 31;
    const int wib  = part * WARPS + warp;          // warp index within batch: 0..31

    // head / tail rows for this batch, register-resident (reused ~8 rows/warp)
    const float4* base = (const float4*)(bridges + (size_t)b * SS * DD);
    const float4* hp   = base;                               // s = 0
    const float4* tp4  = base + (size_t)(SS - 1) * (DD / 4); // s = S-1

    float4 h[8], tl[8];
#pragma unroll
    for (int j = 0; j < 8; j++) {
        h[j]  = hp [lane + j * 32];
        tl[j] = tp4[lane + j * 32];
    }

    const float th = (float)b_inx[b * SS];
    const float tt = (float)b_inx[b * SS + SS - 1];
    const float inv_den = 1.0f / (tt - th);

    float wloss = 0.0f;

    for (int r = wib; r < SS - 2; r += SPLIT * WARPS) {
        const int s = r + 1;
        const float tpv   = (float)b_inx[b * SS + s];
        const float alpha = (tpv - th) * inv_den;
        const float sigma = alpha * (tt - tpv);
        const float inv   = 1.0f / (2.0f * sigma * sigma);

        const int ni = neg_i[b * (SS - 2) + r];
        const int nj = neg_j[b * (SS - 2) + r];

        const float4* pp = (const float4*)(bridges + ((size_t)b  * SS + s ) * DD);
        const float4* np = (const float4*)(bridges + ((size_t)ni * SS + nj) * DD);

        // Three alpha-free accumulators:
        //   A  = sum (n+p)(n-p) = sum (n^2 - p^2)
        //   Bh = sum h * (n-p)
        //   Bt = sum t * (n-p)
        float accA = 0.0f, accBh = 0.0f, accBt = 0.0f;
#pragma unroll
        for (int half = 0; half < 2; half++) {
            float4 p[4], n[4];
#pragma unroll
            for (int j = 0; j < 4; j++) {
                const int idx = lane + (half * 4 + j) * 32;
                p[j] = pp[idx];
                n[j] = np[idx];
            }
#pragma unroll
            for (int j = 0; j < 4; j++) {
                const int jj = half * 4 + j;
                const float4 hv = h[jj], tv = tl[jj], pv = p[j], nv = n[j];
                const float dx = nv.x - pv.x, sx = nv.x + pv.x;
                const float dy = nv.y - pv.y, sy = nv.y + pv.y;
                const float dz = nv.z - pv.z, sz = nv.z + pv.z;
                const float dw = nv.w - pv.w, sw = nv.w + pv.w;
                accA  = fmaf(sx,   dx, accA);
                accBh = fmaf(hv.x, dx, accBh);
                accBt = fmaf(tv.x, dx, accBt);
                accA  = fmaf(sy,   dy, accA);
                accBh = fmaf(hv.y, dy, accBh);
                accBt = fmaf(tv.y, dy, accBt);
                accA  = fmaf(sz,   dz, accA);
                accBh = fmaf(hv.z, dz, accBh);
                accBt = fmaf(tv.z, dz, accBt);
                accA  = fmaf(sw,   dw, accA);
                accBh = fmaf(hv.w, dw, accBh);
                accBt = fmaf(tv.w, dw, accBt);
            }
        }

        // warp tree reduce (3 independent values, shuffles pipeline)
#pragma unroll
        for (int off = 16; off; off >>= 1) {
            accA  += __shfl_xor_sync(0xffffffffu, accA,  off);
            accBh += __shfl_xor_sync(0xffffffffu, accBh, off);
            accBt += __shfl_xor_sync(0xffffffffu, accBt, off);
        }

        // sum(xn^2 - xp^2) = A - 2*((1-alpha)*Bh + alpha*Bt)
        const float mdot = fmaf(alpha, accBt, (1.0f - alpha) * accBh);
        const float diff = fmaf(-2.0f, mdot, accA);
        const float cur  = fmaf(diff, inv, BETA_F);
        if (cur > 0.0f) wloss += cur;
    }

    __shared__ float sm[WARPS];
    __shared__ bool  amLast;
    if (lane == 0) sm[warp] = wloss;
    __syncthreads();
    if (threadIdx.x == 0) {
        float t = 0.0f;
#pragma unroll
        for (int w = 0; w < WARPS; w++) t += sm[w];
        g_partials[blockIdx.x] = t;
        __threadfence();
        // wraps to 0 when old == NBLOCKS-1 -> self-resetting for graph replay
        unsigned old = atomicInc(&g_ctr, NBLOCKS - 1);
        amLast = (old == NBLOCKS - 1);
    }
    __syncthreads();

    if (amLast) {
        // Deterministic final reduction: fixed tree order over g_partials.
        __shared__ float fin[NTHREADS];
        float t = 0.0f;
#pragma unroll
        for (int k = 0; k < NBLOCKS / NTHREADS; k++)
            t += g_partials[threadIdx.x + k * NTHREADS];
        fin[threadIdx.x] = t;
        __syncthreads();
#pragma unroll
        for (int st = NTHREADS / 2; st > 0; st >>= 1) {
            if ((int)threadIdx.x < st) fin[threadIdx.x] += fin[threadIdx.x + st];
            __syncthreads();
        }
        if (threadIdx.x == 0) out[0] = fin[0] / (float)BB;
    }
}

extern "C" void kernel_launch(void* const* d_in, const int* in_sizes, int n_in,
                              void* d_out, int out_size)
{
    const float* bridges = (const float*)d_in[0];
    const int*   b_inx   = (const int*)  d_in[1];
    const int*   neg_i   = (const int*)  d_in[2];
    const int*   neg_j   = (const int*)  d_in[3];

    bridge_loss_fused<<<NBLOCKS, NTHREADS>>>(bridges, b_inx, neg_i, neg_j,
                                             (float*)d_out);
}

// round 5
// speedup vs baseline: 1.7385x; 1.2462x over previous
#include <cuda_runtime.h>

// Problem constants (from reference): B=128, S=256, D=1024, BETA=1.0
#define BB 128
#define SS 256
#define DD 1024
#define BETA_F 1.0f

#define SPLIT 3            // blocks per batch
#define WARPS 4            // warps per block (128 threads)
#define NBLOCKS (BB * SPLIT)        // 384
#define NTHREADS (WARPS * 32)       // 128
#define STEP (SPLIT * WARPS)        // 12 warps cover one batch
#define NROWS (SS - 2)              // 254 interior rows

__device__ float g_partials[NBLOCKS];
__device__ unsigned g_ctr = 0;   // self-resetting via atomicInc wraparound

__global__ __launch_bounds__(NTHREADS, 3)
void bridge_loss_fused(const float* __restrict__ bridges,
                       const int*   __restrict__ b_inx,
                       const int*   __restrict__ neg_i,
                       const int*   __restrict__ neg_j,
                       float*       __restrict__ out)
{
    const int b    = blockIdx.x / SPLIT;
    const int part = blockIdx.x % SPLIT;
    const int warp = threadIdx.x >> 5;
    const int lane = threadIdx.x & 31;
    const int wib  = part * WARPS + warp;          // 0..11

    // head / tail rows, register-resident
    const float4* base = (const float4*)(bridges + (size_t)b * SS * DD);
    const float4* hp   = base;
    const float4* tp4  = base + (size_t)(SS - 1) * (DD / 4);

    float4 h[8], tl[8];
#pragma unroll
    for (int j = 0; j < 8; j++) {
        h[j]  = hp [lane + j * 32];
        tl[j] = tp4[lane + j * 32];
    }

    const float th = (float)b_inx[b * SS];
    const float tt = (float)b_inx[b * SS + SS - 1];
    const float inv_den = 1.0f / (tt - th);

    float wloss = 0.0f;

    int r = wib;
    float4 P[8], N[8];

    // prologue: load first row pair fully (16 LDG.128 in flight)
    if (r < NROWS) {
        const float4* pp = (const float4*)(bridges + ((size_t)b * SS + r + 1) * DD);
        const int ni = neg_i[b * NROWS + r];
        const int nj = neg_j[b * NROWS + r];
        const float4* np = (const float4*)(bridges + ((size_t)ni * SS + nj) * DD);
#pragma unroll
        for (int j = 0; j < 8; j++) {
            P[j] = pp[lane + j * 32];
            N[j] = np[lane + j * 32];
        }
    }

    while (r < NROWS) {
        // scalar params for the current row
        const float tpv   = (float)b_inx[b * SS + r + 1];
        const float alpha = (tpv - th) * inv_den;
        const float sigma = alpha * (tt - tpv);
        const float inv   = 1.0f / (2.0f * sigma * sigma);

        // next-row addresses (issued early so index loads overlap compute)
        const int rn = r + STEP;
        const bool hn = rn < NROWS;
        const float4* ppn = (const float4*)base;   // safe dummy
        const float4* npn = (const float4*)base;
        if (hn) {
            ppn = (const float4*)(bridges + ((size_t)b * SS + rn + 1) * DD);
            const int ni = neg_i[b * NROWS + rn];
            const int nj = neg_j[b * NROWS + rn];
            npn = (const float4*)(bridges + ((size_t)ni * SS + nj) * DD);
        }

        // A  = sum (n^2 - p^2);  Bh = sum h*(n-p);  Bt = sum t*(n-p)
        float accA = 0.0f, accBh = 0.0f, accBt = 0.0f;
#pragma unroll
        for (int j = 0; j < 8; j++) {
            const float4 pv = P[j], nv = N[j];
            // prefetch row rn chunk j while computing row r chunk j
            if (hn) {
                P[j] = ppn[lane + j * 32];
                N[j] = npn[lane + j * 32];
            }
            const float4 hv = h[j], tv = tl[j];
            const float dx = nv.x - pv.x, sx = nv.x + pv.x;
            const float dy = nv.y - pv.y, sy = nv.y + pv.y;
            const float dz = nv.z - pv.z, sz = nv.z + pv.z;
            const float dw = nv.w - pv.w, sw = nv.w + pv.w;
            accA  = fmaf(sx,   dx, accA);
            accBh = fmaf(hv.x, dx, accBh);
            accBt = fmaf(tv.x, dx, accBt);
            accA  = fmaf(sy,   dy, accA);
            accBh = fmaf(hv.y, dy, accBh);
            accBt = fmaf(tv.y, dy, accBt);
            accA  = fmaf(sz,   dz, accA);
            accBh = fmaf(hv.z, dz, accBh);
            accBt = fmaf(tv.z, dz, accBt);
            accA  = fmaf(sw,   dw, accA);
            accBh = fmaf(hv.w, dw, accBh);
            accBt = fmaf(tv.w, dw, accBt);
        }

        // warp tree reduce (3 independent values pipeline; next-row loads in flight)
#pragma unroll
        for (int off = 16; off; off >>= 1) {
            accA  += __shfl_xor_sync(0xffffffffu, accA,  off);
            accBh += __shfl_xor_sync(0xffffffffu, accBh, off);
            accBt += __shfl_xor_sync(0xffffffffu, accBt, off);
        }

        // sum(xn^2 - xp^2) = A - 2*((1-alpha)*Bh + alpha*Bt)
        const float mdot = fmaf(alpha, accBt, (1.0f - alpha) * accBh);
        const float diff = fmaf(-2.0f, mdot, accA);
        const float cur  = fmaf(diff, inv, BETA_F);
        if (cur > 0.0f) wloss += cur;

        r = rn;
    }

    __shared__ float sm[WARPS];
    __shared__ bool  amLast;
    if (lane == 0) sm[warp] = wloss;
    __syncthreads();
    if (threadIdx.x == 0) {
        float t = 0.0f;
#pragma unroll
        for (int w = 0; w < WARPS; w++) t += sm[w];
        g_partials[blockIdx.x] = t;
        __threadfence();
        unsigned old = atomicInc(&g_ctr, NBLOCKS - 1);   // wraps -> replay safe
        amLast = (old == NBLOCKS - 1);
    }
    __syncthreads();

    if (amLast) {
        __shared__ float fin[NTHREADS];
        float t = 0.0f;
#pragma unroll
        for (int k = 0; k < NBLOCKS / NTHREADS; k++)
            t += g_partials[threadIdx.x + k * NTHREADS];
        fin[threadIdx.x] = t;
        __syncthreads();
#pragma unroll
        for (int st = NTHREADS / 2; st > 0; st >>= 1) {
            if ((int)threadIdx.x < st) fin[threadIdx.x] += fin[threadIdx.x + st];
            __syncthreads();
        }
        if (threadIdx.x == 0) out[0] = fin[0] / (float)BB;
    }
}

extern "C" void kernel_launch(void* const* d_in, const int* in_sizes, int n_in,
                              void* d_out, int out_size)
{
    const float* bridges = (const float*)d_in[0];
    const int*   b_inx   = (const int*)  d_in[1];
    const int*   neg_i   = (const int*)  d_in[2];
    const int*   neg_j   = (const int*)  d_in[3];

    bridge_loss_fused<<<NBLOCKS, NTHREADS>>>(bridges, b_inx, neg_i, neg_j,
                                             (float*)d_out);
}

// round 6
// speedup vs baseline: 1.8374x; 1.0569x over previous
#include <cuda_runtime.h>

// Problem constants (from reference): B=128, S=256, D=1024, BETA=1.0
#define BB 128
#define SS 256
#define DD 1024
#define BETA_F 1.0f

#define NSM 148
#define BLOCKS_PER_SM 3
#define WARPS 4                        // warps per block (128 threads)
#define NBLOCKS (NSM * BLOCKS_PER_SM)  // 444 — exactly fills one wave at occ=3
#define NTHREADS (WARPS * 32)          // 128
#define NWARPS_TOTAL (NBLOCKS * WARPS) // 1776
#define NROWS (SS - 2)                 // 254 interior rows per batch
#define TOTAL_ROWS (BB * NROWS)        // 32512

__device__ float g_partials[NBLOCKS];
__device__ unsigned g_ctr = 0;   // self-resetting via atomicInc wraparound

// Process rows [r0, r1) of batch b (contiguous), software-pipelined.
__device__ __forceinline__ float process_segment(
    const float* __restrict__ bridges,
    const int*   __restrict__ b_inx,
    const int*   __restrict__ neg_i,
    const int*   __restrict__ neg_j,
    int b, int r0, int r1, int lane)
{
    const float4* base = (const float4*)(bridges + (size_t)b * SS * DD);
    const float4* hp   = base;
    const float4* tp4  = base + (size_t)(SS - 1) * (DD / 4);

    float4 h[8], tl[8];
#pragma unroll
    for (int j = 0; j < 8; j++) {
        h[j]  = hp [lane + j * 32];
        tl[j] = tp4[lane + j * 32];
    }

    const float th = (float)b_inx[b * SS];
    const float tt = (float)b_inx[b * SS + SS - 1];
    const float inv_den = 1.0f / (tt - th);

    float wloss = 0.0f;

    int r = r0;
    float4 P[8], N[8];

    // prologue: first row pair fully in flight (16 LDG.128)
    {
        const float4* pp = (const float4*)(bridges + ((size_t)b * SS + r + 1) * DD);
        const int ni = neg_i[b * NROWS + r];
        const int nj = neg_j[b * NROWS + r];
        const float4* np = (const float4*)(bridges + ((size_t)ni * SS + nj) * DD);
#pragma unroll
        for (int j = 0; j < 8; j++) {
            P[j] = pp[lane + j * 32];
            N[j] = np[lane + j * 32];
        }
    }

    while (r < r1) {
        const float tpv   = (float)b_inx[b * SS + r + 1];
        const float alpha = (tpv - th) * inv_den;
        const float sigma = alpha * (tt - tpv);
        const float inv   = 1.0f / (2.0f * sigma * sigma);

        const int rn = r + 1;
        const bool hn = rn < r1;
        const float4* ppn = (const float4*)base;   // safe dummy
        const float4* npn = (const float4*)base;
        if (hn) {
            ppn = (const float4*)(bridges + ((size_t)b * SS + rn + 1) * DD);
            const int ni = neg_i[b * NROWS + rn];
            const int nj = neg_j[b * NROWS + rn];
            npn = (const float4*)(bridges + ((size_t)ni * SS + nj) * DD);
        }

        // A = sum (n^2 - p^2); Bh = sum h*(n-p); Bt = sum t*(n-p)
        float accA = 0.0f, accBh = 0.0f, accBt = 0.0f;
#pragma unroll
        for (int j = 0; j < 8; j++) {
            const float4 pv = P[j], nv = N[j];
            if (hn) {                        // prefetch next row, chunk j
                P[j] = ppn[lane + j * 32];
                N[j] = npn[lane + j * 32];
            }
            const float4 hv = h[j], tv = tl[j];
            const float dx = nv.x - pv.x, sx = nv.x + pv.x;
            const float dy = nv.y - pv.y, sy = nv.y + pv.y;
            const float dz = nv.z - pv.z, sz = nv.z + pv.z;
            const float dw = nv.w - pv.w, sw = nv.w + pv.w;
            accA  = fmaf(sx,   dx, accA);
            accBh = fmaf(hv.x, dx, accBh);
            accBt = fmaf(tv.x, dx, accBt);
            accA  = fmaf(sy,   dy, accA);
            accBh = fmaf(hv.y, dy, accBh);
            accBt = fmaf(tv.y, dy, accBt);
            accA  = fmaf(sz,   dz, accA);
            accBh = fmaf(hv.z, dz, accBh);
            accBt = fmaf(tv.z, dz, accBt);
            accA  = fmaf(sw,   dw, accA);
            accBh = fmaf(hv.w, dw, accBh);
            accBt = fmaf(tv.w, dw, accBt);
        }

#pragma unroll
        for (int off = 16; off; off >>= 1) {
            accA  += __shfl_xor_sync(0xffffffffu, accA,  off);
            accBh += __shfl_xor_sync(0xffffffffu, accBh, off);
            accBt += __shfl_xor_sync(0xffffffffu, accBt, off);
        }

        const float mdot = fmaf(alpha, accBt, (1.0f - alpha) * accBh);
        const float diff = fmaf(-2.0f, mdot, accA);
        const float cur  = fmaf(diff, inv, BETA_F);
        if (cur > 0.0f) wloss += cur;

        r = rn;
    }
    return wloss;
}

__global__ __launch_bounds__(NTHREADS, BLOCKS_PER_SM)
void bridge_loss_fused(const float* __restrict__ bridges,
                       const int*   __restrict__ b_inx,
                       const int*   __restrict__ neg_i,
                       const int*   __restrict__ neg_j,
                       float*       __restrict__ out)
{
    const int warp = threadIdx.x >> 5;
    const int lane = threadIdx.x & 31;
    const int gw   = blockIdx.x * WARPS + warp;   // 0..1775

    // balanced contiguous chunk of the flattened (b, r) row space
    int start = (int)(((long long)gw       * TOTAL_ROWS) / NWARPS_TOTAL);
    int end   = (int)(((long long)(gw + 1) * TOTAL_ROWS) / NWARPS_TOTAL);

    float wloss = 0.0f;
    while (start < end) {
        const int b  = start / NROWS;
        const int r0 = start - b * NROWS;
        const int r1 = min(end - b * NROWS, NROWS);
        wloss += process_segment(bridges, b_inx, neg_i, neg_j, b, r0, r1, lane);
        start = b * NROWS + r1;
    }

    __shared__ float sm[WARPS];
    __shared__ bool  amLast;
    if (lane == 0) sm[warp] = wloss;
    __syncthreads();
    if (threadIdx.x == 0) {
        float t = 0.0f;
#pragma unroll
        for (int w = 0; w < WARPS; w++) t += sm[w];
        g_partials[blockIdx.x] = t;
        __threadfence();
        unsigned old = atomicInc(&g_ctr, NBLOCKS - 1);   // wraps -> replay safe
        amLast = (old == NBLOCKS - 1);
    }
    __syncthreads();

    if (amLast) {
        __shared__ float fin[NTHREADS];
        float t = 0.0f;
#pragma unroll
        for (int k = 0; k < (NBLOCKS + NTHREADS - 1) / NTHREADS; k++) {
            const int idx = threadIdx.x + k * NTHREADS;
            if (idx < NBLOCKS) t += g_partials[idx];
        }
        fin[threadIdx.x] = t;
        __syncthreads();
#pragma unroll
        for (int st = NTHREADS / 2; st > 0; st >>= 1) {
            if ((int)threadIdx.x < st) fin[threadIdx.x] += fin[threadIdx.x + st];
            __syncthreads();
        }
        if (threadIdx.x == 0) out[0] = fin[0] / (float)BB;
    }
}

extern "C" void kernel_launch(void* const* d_in, const int* in_sizes, int n_in,
                              void* d_out, int out_size)
{
    const float* bridges = (const float*)d_in[0];
    const int*   b_inx   = (const int*)  d_in[1];
    const int*   neg_i   = (const int*)  d_in[2];
    const int*   neg_j   = (const int*)  d_in[3];

    bridge_loss_fused<<<NBLOCKS, NTHREADS>>>(bridges, b_inx, neg_i, neg_j,
                                             (float*)d_out);
}